// round 14
// baseline (speedup 1.0000x reference)
#include <cuda_runtime.h>
#include <cuda_bf16.h>
#include <math.h>
#include <stdint.h>

#define NS 2048
#define DD 256
#define NF 4096
#define HALF ((long long)NS*DD)
#define LL2  ((long long)NS*512)
#define NELEM ((long long)NS*NS)
#define NFDD ((long long)NF*DD)
#define SUPCON_SCALE 14.285714285714286f

// ---------------- persistent streams/events ----------------
struct StreamInit {
    cudaStream_t s;
    cudaEvent_t ev[6];
    StreamInit(){
        cudaStreamCreateWithFlags(&s, cudaStreamNonBlocking);
        for (int i = 0; i < 6; i++) cudaEventCreateWithFlags(&ev[i], cudaEventDisableTiming);
    }
};
static StreamInit g_si;

// ---------------- helpers ----------------
__device__ __forceinline__ uint32_t smem_to_u32(const void* p){
    uint32_t a;
    asm("{ .reg .u64 t; cvta.to.shared.u64 t, %1; cvt.u32.u64 %0, t; }" : "=r"(a) : "l"(p));
    return a;
}
__device__ __forceinline__ void cp16(void* s, const void* g){
    uint32_t sa = smem_to_u32(s);
    asm volatile("cp.async.ca.shared.global [%0], [%1], 16;" :: "r"(sa), "l"(g) : "memory");
}
__device__ __forceinline__ void ldsm_x4(uint32_t* r, uint32_t addr){
    asm volatile("ldmatrix.sync.aligned.m8n8.x4.shared.b16 {%0,%1,%2,%3}, [%4];"
        : "=r"(r[0]), "=r"(r[1]), "=r"(r[2]), "=r"(r[3]) : "r"(addr));
}
__device__ __forceinline__ void ldsm_x2(uint32_t* r, uint32_t addr){
    asm volatile("ldmatrix.sync.aligned.m8n8.x2.shared.b16 {%0,%1}, [%2];"
        : "=r"(r[0]), "=r"(r[1]) : "r"(addr));
}
__device__ __forceinline__ void ldsm_x2t(uint32_t* r, uint32_t addr){
    asm volatile("ldmatrix.sync.aligned.m8n8.x2.trans.shared.b16 {%0,%1}, [%2];"
        : "=r"(r[0]), "=r"(r[1]) : "r"(addr));
}
__device__ __forceinline__ void mma16816(float* c, const uint32_t* a, const uint32_t* b){
    asm volatile("mma.sync.aligned.m16n8k16.row.col.f32.bf16.bf16.f32 "
        "{%0,%1,%2,%3}, {%4,%5,%6,%7}, {%8,%9}, {%0,%1,%2,%3};"
        : "+f"(c[0]), "+f"(c[1]), "+f"(c[2]), "+f"(c[3])
        : "r"(a[0]), "r"(a[1]), "r"(a[2]), "r"(a[3]), "r"(b[0]), "r"(b[1]));
}
__device__ __forceinline__ float fexp(float x){
    float t = x * 1.4426950408889634f;
    float r = rintf(t);
    float f = t - r;
    float p =            1.3333558146e-3f;
    p = fmaf(p, f, 9.6181291076e-3f);
    p = fmaf(p, f, 5.5504108664e-2f);
    p = fmaf(p, f, 2.4022650696e-1f);
    p = fmaf(p, f, 6.9314718056e-1f);
    p = fmaf(p, f, 1.0f);
    float res = __int_as_float(__float_as_int(p) + (((int)r) << 23));
    return (x < -87.0f) ? 0.0f : res;
}
__device__ __forceinline__ float bsum256(float v, float* red){
    int tid = threadIdx.x;
    red[tid] = v; __syncthreads();
    #pragma unroll
    for (int o = 128; o > 0; o >>= 1){
        if (tid < o) red[tid] += red[tid + o];
        __syncthreads();
    }
    float r = red[0]; __syncthreads();
    return r;
}
__device__ __forceinline__ float wsum(float v){
    #pragma unroll
    for (int o = 16; o > 0; o >>= 1) v += __shfl_xor_sync(0xffffffffu, v, o);
    return v;
}

// ---------------- scratch ----------------
__device__ __nv_bfloat16 g_inb[NF*DD], g_h1b[NF*DD], g_x0b[NF*DD], g_x1b[NF*DD], g_x2b[NF*DD];
__device__ __nv_bfloat16 g_qb[NF*DD], g_fnb[NF*DD];
__device__ __nv_bfloat16 g_qkv[(long long)NF*512];
__device__ __nv_bfloat16 g_Pb[2*NELEM];
__device__ __nv_bfloat16 g_wT[17*DD*DD];
__device__ float g_x0[NF*DD], g_x1[NF*DD], g_x2[NF*DD];
__device__ float g_S0[NELEM];
__device__ float g_rsum[2*NF], g_r[NS], g_c[NS], g_ep[2*NF];
__device__ double g_dacc[4];
__device__ int g_lab[NF], g_hist[16];
__device__ int g_cnt;
__device__ volatile int g_epoch;

// ============================================================================
// Generic bf16 HMMA NT/NN GEMM, 128x128 tile, K-chunk 32, double-buffered
// cp.async (41 KB smem -> 2 CTAs/SM).
// epi: 0 bf16 | 1 f32+bias | 3 exp+rowsum+bf16 | 4 split-K f32 slice
//      5 bf16 store + stats | 6 supcon triangular row+col
// ============================================================================
__global__ __launch_bounds__(256)
void tc_nt(const __nv_bfloat16* A, int lda, long long azs,
           const __nv_bfloat16* B, int ldb, long long bzs, int transB,
           int K, int ksl, int epi, float scale, int scaleN,
           float* outF, __nv_bfloat16* outB, int ldc, long long czs, int mzoff,
           const float* bias, float* rsumW, double* dacc,
           const int* lab, float* esum, float* psum)
{
    if (epi == 6 && blockIdx.x < blockIdx.y) return;
    __shared__ __nv_bfloat16 SA[2][128*40];
    __shared__ __nv_bfloat16 SB[2][128*40];
    __shared__ float red[256];

    int z = blockIdx.z;
    int dom = z / ksl, kk = z - dom*ksl;
    A += (long long)dom * azs;
    B += (long long)dom * bzs;
    if (outB) outB += (long long)dom * czs;

    int tid = threadIdx.x, wid = tid >> 5, lane = tid & 31;
    int wr = wid >> 2, wc = wid & 3;
    int row0 = blockIdx.y * 128, col0 = blockIdx.x * 128;

    float acc[4][4][4];
    #pragma unroll
    for (int mi = 0; mi < 4; mi++)
        #pragma unroll
        for (int ni = 0; ni < 4; ni++)
            #pragma unroll
            for (int q = 0; q < 4; q++) acc[mi][ni][q] = 0.f;

    int aRow  = wr*64 + (lane & 7) + ((lane >> 3) & 1)*8;
    int aKoff = (lane >> 4)*8;
    int l16   = lane & 15;
    int bRow  = wc*32 + (l16 & 7);
    int bKoff = (l16 >> 3)*8;

    int nch = K >> 5;
    int c0ch = kk * nch / ksl, c1ch = (kk+1) * nch / ksl;

    auto load_chunk = [&](int c, int buf){
        int kc = c << 5;
        #pragma unroll
        for (int i = 0; i < 2; i++){
            int lin = i*256 + tid;
            int r = lin >> 2, c8 = (lin & 3) << 3;
            cp16(&SA[buf][r*40 + c8], A + (size_t)(row0+r)*lda + kc + c8);
        }
        if (!transB){
            #pragma unroll
            for (int i = 0; i < 2; i++){
                int lin = i*256 + tid;
                int r = lin >> 2, c8 = (lin & 3) << 3;
                cp16(&SB[buf][r*40 + c8], B + (size_t)(col0+r)*ldb + kc + c8);
            }
        } else {
            #pragma unroll
            for (int i = 0; i < 2; i++){
                int lin = i*256 + tid;
                int r = lin >> 4, c8 = (lin & 15) << 3;
                cp16(&SB[buf][r*136 + c8], B + (size_t)(kc+r)*ldb + col0 + c8);
            }
        }
    };

    load_chunk(c0ch, 0);
    asm volatile("cp.async.commit_group;" ::: "memory");
    asm volatile("cp.async.wait_group 0;" ::: "memory");
    __syncthreads();

    for (int c = c0ch; c < c1ch; c++){
        int buf = (c - c0ch) & 1;
        if (c + 1 < c1ch){
            load_chunk(c+1, buf^1);
            asm volatile("cp.async.commit_group;" ::: "memory");
        }
        uint32_t sAb = smem_to_u32(SA[buf]);
        uint32_t sBb = smem_to_u32(SB[buf]);
        #pragma unroll
        for (int ks = 0; ks < 2; ks++){
            uint32_t af[4][4], bf[4][2];
            #pragma unroll
            for (int mi = 0; mi < 4; mi++)
                ldsm_x4(af[mi], sAb + (uint32_t)(((aRow + mi*16)*40 + ks*16 + aKoff) * 2));
            if (!transB){
                #pragma unroll
                for (int ni = 0; ni < 4; ni++)
                    ldsm_x2(bf[ni], sBb + (uint32_t)(((bRow + ni*8)*40 + ks*16 + bKoff) * 2));
            } else {
                #pragma unroll
                for (int ni = 0; ni < 4; ni++)
                    ldsm_x2t(bf[ni], sBb + (uint32_t)(((ks*16 + l16)*136 + wc*32 + ni*8) * 2));
            }
            #pragma unroll
            for (int mi = 0; mi < 4; mi++)
                #pragma unroll
                for (int ni = 0; ni < 4; ni++)
                    mma16816(acc[mi][ni], af[mi], bf[ni]);
        }
        if (c + 1 < c1ch)
            asm volatile("cp.async.wait_group 0;" ::: "memory");
        __syncthreads();
    }

    int lr = lane >> 2, lc2 = (lane & 3) << 1;
    int colB = col0 + wc*32;
    float s1 = 0.f, s2 = 0.f;
    bool diag = (blockIdx.x == blockIdx.y);
    float colE[8], colS[8];
    #pragma unroll
    for (int q = 0; q < 8; q++){ colE[q] = 0.f; colS[q] = 0.f; }
    int labc[8];
    if (epi == 6){
        #pragma unroll
        for (int ni = 0; ni < 4; ni++){
            labc[ni*2]   = lab[colB + ni*8 + lc2];
            labc[ni*2+1] = lab[colB + ni*8 + lc2 + 1];
        }
    }

    #pragma unroll
    for (int mi = 0; mi < 4; mi++){
        #pragma unroll
        for (int h = 0; h < 2; h++){
            int r = row0 + wr*64 + mi*16 + lr + h*8;
            if (epi == 0){
                #pragma unroll
                for (int ni = 0; ni < 4; ni++){
                    int cc = colB + ni*8 + lc2;
                    float m0 = (cc   < scaleN) ? scale : 1.0f;
                    float m1 = (cc+1 < scaleN) ? scale : 1.0f;
                    float v0 = acc[mi][ni][h*2+0]*m0, v1 = acc[mi][ni][h*2+1]*m1;
                    *(__nv_bfloat162*)(outB + (size_t)r*ldc + cc) = __floats2bfloat162_rn(v0, v1);
                }
            } else if (epi == 1){
                #pragma unroll
                for (int ni = 0; ni < 4; ni++){
                    int cc = colB + ni*8 + lc2;
                    float2 o = make_float2(acc[mi][ni][h*2+0] + bias[cc],
                                           acc[mi][ni][h*2+1] + bias[cc+1]);
                    *(float2*)(outF + (size_t)r*ldc + cc) = o;
                }
            } else if (epi == 3){
                float part = 0.f;
                #pragma unroll
                for (int ni = 0; ni < 4; ni++){
                    int cc = colB + ni*8 + lc2;
                    float e0 = fexp(acc[mi][ni][h*2+0]), e1 = fexp(acc[mi][ni][h*2+1]);
                    part += e0 + e1;
                    *(__nv_bfloat162*)(outB + (size_t)r*ldc + cc) = __floats2bfloat162_rn(e0, e1);
                }
                part += __shfl_xor_sync(0xffffffffu, part, 1);
                part += __shfl_xor_sync(0xffffffffu, part, 2);
                if ((lane & 3) == 0) atomicAdd(&rsumW[dom*mzoff + r], part);
            } else if (epi == 4){
                int mg = dom*mzoff + r;
                #pragma unroll
                for (int ni = 0; ni < 4; ni++){
                    int cc = colB + ni*8 + lc2;
                    *(float2*)(outF + (long long)kk*NFDD + (size_t)mg*ldc + cc) =
                        make_float2(acc[mi][ni][h*2+0], acc[mi][ni][h*2+1]);
                }
            } else if (epi == 5){
                #pragma unroll
                for (int ni = 0; ni < 4; ni++){
                    int cc = colB + ni*8 + lc2;
                    float v0 = acc[mi][ni][h*2+0], v1 = acc[mi][ni][h*2+1];
                    *(__nv_bfloat162*)(outB + (size_t)r*ldc + cc) = __floats2bfloat162_rn(v0, v1);
                    s1 += v0 + v1; s2 += v0*v0 + v1*v1;
                }
            } else {
                int rlab = lab[r];
                float pe = 0.f, ps = 0.f;
                #pragma unroll
                for (int ni = 0; ni < 4; ni++){
                    int cc = colB + ni*8 + lc2;
                    float l0 = acc[mi][ni][h*2+0]*scale, l1 = acc[mi][ni][h*2+1]*scale;
                    bool m0 = (labc[ni*2]   == rlab);
                    bool m1 = (labc[ni*2+1] == rlab);
                    if (cc != r){
                        float e = fexp(l0);
                        pe += e; if (m0) ps += l0;
                        if (!diag){ colE[ni*2] += e; if (m0) colS[ni*2] += l0; }
                    }
                    if (cc+1 != r){
                        float e = fexp(l1);
                        pe += e; if (m1) ps += l1;
                        if (!diag){ colE[ni*2+1] += e; if (m1) colS[ni*2+1] += l1; }
                    }
                }
                pe += __shfl_xor_sync(0xffffffffu, pe, 1);
                pe += __shfl_xor_sync(0xffffffffu, pe, 2);
                ps += __shfl_xor_sync(0xffffffffu, ps, 1);
                ps += __shfl_xor_sync(0xffffffffu, ps, 2);
                if ((lane & 3) == 0){
                    atomicAdd(&esum[r], pe);
                    atomicAdd(&psum[r], ps);
                }
            }
        }
    }
    if (epi == 6 && !diag){
        #pragma unroll
        for (int q = 0; q < 8; q++){
            #pragma unroll
            for (int o = 4; o <= 16; o <<= 1){
                colE[q] += __shfl_xor_sync(0xffffffffu, colE[q], o);
                colS[q] += __shfl_xor_sync(0xffffffffu, colS[q], o);
            }
        }
        if (lane < 4){
            #pragma unroll
            for (int ni = 0; ni < 4; ni++){
                int cc = col0 + wc*32 + ni*8 + lane*2;
                atomicAdd(&esum[cc],   colE[ni*2]);
                atomicAdd(&psum[cc],   colS[ni*2]);
                atomicAdd(&esum[cc+1], colE[ni*2+1]);
                atomicAdd(&psum[cc+1], colS[ni*2+1]);
            }
        }
    }
    if (epi == 5){
        float bs = bsum256(s1, red), bss = bsum256(s2, red);
        if (tid == 0){ atomicAdd(dacc, (double)bs); atomicAdd(dacc+1, (double)bss); }
    }
}

// ---------------- small kernels ----------------
__global__ __launch_bounds__(256)
void cvt_in(const float* __restrict__ a, const float* __restrict__ b,
            __nv_bfloat16* __restrict__ o, const int* __restrict__ lab, int* hist){
    int i = blockIdx.x, t = threadIdx.x;
    const float* src = (i < NS) ? a + (size_t)i*DD : b + (size_t)(i-NS)*DD;
    o[(size_t)i*DD + t] = __float2bfloat16(src[t]);
    if (t == 0) atomicAdd(&hist[lab[i]], 1);
}
struct P17 { const float* p[17]; int tr[17]; float sc[17]; };
__global__ __launch_bounds__(256)
void cvtT17(P17 s, __nv_bfloat16* __restrict__ o){
    int w = blockIdx.y, n = blockIdx.x, k = threadIdx.x;
    const float* src = s.p[w];
    if (!src) return;
    float v = s.tr[w] ? src[(size_t)k*DD + n] : src[(size_t)n*DD + k];
    o[(size_t)w*DD*DD + (size_t)n*DD + k] = __float2bfloat16(v * s.sc[w]);
}
__global__ __launch_bounds__(256)
void ln2_fast(const float* __restrict__ S, const float* __restrict__ bias,
              float* __restrict__ outF, __nv_bfloat16* __restrict__ outB, int relu){
    int wid = threadIdx.x >> 5, lane = threadIdx.x & 31;
    int i = blockIdx.x*8 + wid;
    size_t off = (size_t)i*DD + lane*8;
    float4 a0 = *(const float4*)(S + off);
    float4 b0 = *(const float4*)(S + off + 4);
    float4 a1 = *(const float4*)(S + NFDD + off);
    float4 b1 = *(const float4*)(S + NFDD + off + 4);
    const float* bp = bias + lane*8;
    float v[8];
    v[0]=a0.x+a1.x+bp[0]; v[1]=a0.y+a1.y+bp[1]; v[2]=a0.z+a1.z+bp[2]; v[3]=a0.w+a1.w+bp[3];
    v[4]=b0.x+b1.x+bp[4]; v[5]=b0.y+b1.y+bp[5]; v[6]=b0.z+b1.z+bp[6]; v[7]=b0.w+b1.w+bp[7];
    float s = 0.f, ss = 0.f;
    #pragma unroll
    for (int q = 0; q < 8; q++){ s += v[q]; ss += v[q]*v[q]; }
    s = wsum(s); ss = wsum(ss);
    float m = s*(1.f/DD);
    float k = rsqrtf(ss*(1.f/DD) - m*m + 1e-5f);
    __nv_bfloat162 ob[4];
    #pragma unroll
    for (int q = 0; q < 4; q++){
        float o0 = (v[2*q]   - m)*k;
        float o1 = (v[2*q+1] - m)*k;
        if (relu){ o0 = fmaxf(o0, 0.f); o1 = fmaxf(o1, 0.f); }
        if (outF) *(float2*)(outF + off + 2*q) = make_float2(o0, o1);
        ob[q] = __floats2bfloat162_rn(o0, o1);
    }
    *(uint4*)(outB + off) = *(uint4*)ob;
}
__global__ __launch_bounds__(256)
void fnorm_fast(const float* __restrict__ X, __nv_bfloat16* __restrict__ F){
    int wid = threadIdx.x >> 5, lane = threadIdx.x & 31;
    int i = blockIdx.x*8 + wid;
    const float* xp = X + (size_t)i*DD + lane*8;
    float4 a = *(const float4*)xp;
    float4 b = *(const float4*)(xp + 4);
    float ss = a.x*a.x+a.y*a.y+a.z*a.z+a.w*a.w + b.x*b.x+b.y*b.y+b.z*b.z+b.w*b.w;
    ss = wsum(ss);
    float k = 1.0f / (sqrtf(ss) + 1e-8f);
    float v[8] = {a.x,a.y,a.z,a.w,b.x,b.y,b.z,b.w};
    __nv_bfloat162 ob[4];
    #pragma unroll
    for (int q = 0; q < 4; q++)
        ob[q] = __floats2bfloat162_rn(v[2*q]*k, v[2*q+1]*k);
    *(uint4*)(F + (size_t)i*DD + lane*8) = *(uint4*)ob;
}
__global__ __launch_bounds__(256)
void pv_fin(const float* __restrict__ acc4, const float* __restrict__ rsum,
            const float* __restrict__ res, float* __restrict__ outF,
            __nv_bfloat16* __restrict__ outB){
    int wid = threadIdx.x >> 5, lane = threadIdx.x & 31;
    int i = blockIdx.x*8 + wid;
    float rinv = 1.0f / rsum[i];
    size_t off = (size_t)i*DD + lane*8;
    float v[8];
    #pragma unroll
    for (int q = 0; q < 8; q++) v[q] = 0.f;
    #pragma unroll
    for (int sl = 0; sl < 4; sl++){
        const float* p = acc4 + (long long)sl*NFDD + off;
        float4 a = *(const float4*)p;
        float4 b = *(const float4*)(p + 4);
        v[0]+=a.x; v[1]+=a.y; v[2]+=a.z; v[3]+=a.w;
        v[4]+=b.x; v[5]+=b.y; v[6]+=b.z; v[7]+=b.w;
    }
    const float* rp = res + off;
    float4 ra = *(const float4*)rp;
    float4 rb = *(const float4*)(rp + 4);
    float rr[8] = {ra.x,ra.y,ra.z,ra.w,rb.x,rb.y,rb.z,rb.w};
    __nv_bfloat162 ob[4];
    #pragma unroll
    for (int q = 0; q < 4; q++){
        float o0 = fmaf(v[2*q],   rinv, rr[2*q]);
        float o1 = fmaf(v[2*q+1], rinv, rr[2*q+1]);
        *(float2*)(outF + off + 2*q) = make_float2(o0, o1);
        ob[q] = __floats2bfloat162_rn(o0, o1);
    }
    *(uint4*)(outB + off) = *(uint4*)ob;
}
// Persistent: phase0 builds E/ET from bf16 Sb + stats, then 20 passes + match.
__global__ __launch_bounds__(256)
void sinkhorn_all(const __nv_bfloat16* __restrict__ Sb, const double* __restrict__ dacc,
                  __nv_bfloat16* __restrict__ E, __nv_bfloat16* __restrict__ ET,
                  float* __restrict__ rv, float* __restrict__ cvv,
                  const int* __restrict__ lab, double* acc){
    __shared__ float sm[64][68];
    int tid = threadIdx.x, wid = tid >> 5, lane = tid & 31;
    int row = blockIdx.x*8 + wid;
    int nb = gridDim.x;

    {
        double n = (double)NELEM;
        double mu_d = dacc[0] / n;
        double var = dacc[1] / n - mu_d*mu_d;
        float inv = (float)(1.0 / (sqrt(var) + 1e-5));
        float muinv = (float)mu_d * inv;
        for (int t4 = 0; t4 < 4; t4++){
            int tile = t4*256 + blockIdx.x;
            int r0 = (tile >> 5)*64, c0 = (tile & 31)*64;
            #pragma unroll
            for (int i = 0; i < 2; i++){
                int lin = i*256 + tid;
                int r = lin >> 3, c8 = (lin & 7) << 3;
                uint4 u = *(const uint4*)(Sb + (size_t)(r0+r)*NS + c0 + c8);
                float2 v0 = __bfloat1622float2(*(__nv_bfloat162*)&u.x);
                float2 v1 = __bfloat1622float2(*(__nv_bfloat162*)&u.y);
                float2 v2 = __bfloat1622float2(*(__nv_bfloat162*)&u.z);
                float2 v3 = __bfloat1622float2(*(__nv_bfloat162*)&u.w);
                sm[r][c8+0] = fexp(fmaf(v0.x, inv, -muinv));
                sm[r][c8+1] = fexp(fmaf(v0.y, inv, -muinv));
                sm[r][c8+2] = fexp(fmaf(v1.x, inv, -muinv));
                sm[r][c8+3] = fexp(fmaf(v1.y, inv, -muinv));
                sm[r][c8+4] = fexp(fmaf(v2.x, inv, -muinv));
                sm[r][c8+5] = fexp(fmaf(v2.y, inv, -muinv));
                sm[r][c8+6] = fexp(fmaf(v3.x, inv, -muinv));
                sm[r][c8+7] = fexp(fmaf(v3.y, inv, -muinv));
            }
            __syncthreads();
            #pragma unroll
            for (int i = 0; i < 2; i++){
                int lin = i*256 + tid;
                int r = lin >> 3, g8 = (lin & 7) << 3;
                __nv_bfloat162 ob[4];
                #pragma unroll
                for (int q = 0; q < 4; q++)
                    ob[q] = __floats2bfloat162_rn(sm[r][g8+2*q], sm[r][g8+2*q+1]);
                *(uint4*)(E + (size_t)(r0+r)*NS + c0 + g8) = *(uint4*)ob;
                #pragma unroll
                for (int q = 0; q < 4; q++)
                    ob[q] = __floats2bfloat162_rn(sm[g8+2*q][r], sm[g8+2*q+1][r]);
                *(uint4*)(ET + (size_t)(c0+r)*NS + r0 + g8) = *(uint4*)ob;
            }
            __syncthreads();
        }
    }
    auto gbar = [&](){
        __threadfence();
        __syncthreads();
        if (tid == 0){
            int e = g_epoch;
            if (atomicAdd(&g_cnt, 1) == nb - 1){
                g_cnt = 0;
                __threadfence();
                g_epoch = e + 1;
            } else {
                while (g_epoch == e) { }
            }
            __threadfence();
        }
        __syncthreads();
    };
    gbar();

    for (int pass = 0; pass < 20; pass++){
        const __nv_bfloat16* M = (pass & 1) ? ET : E;
        const float* in = (pass & 1) ? rv : cvv;
        float* out = (pass & 1) ? cvv : rv;
        float s = 0.f;
        #pragma unroll
        for (int b = 0; b < 8; b++){
            int j = (b*32 + lane)*8;
            uint4 u = *(const uint4*)(M + (size_t)row*NS + j);
            float2 e0 = __bfloat1622float2(*(__nv_bfloat162*)&u.x);
            float2 e1 = __bfloat1622float2(*(__nv_bfloat162*)&u.y);
            float2 e2 = __bfloat1622float2(*(__nv_bfloat162*)&u.z);
            float2 e3 = __bfloat1622float2(*(__nv_bfloat162*)&u.w);
            if (pass == 0){
                s += e0.x+e0.y+e1.x+e1.y+e2.x+e2.y+e3.x+e3.y;
            } else {
                float4 c0 = *(const float4*)(in + j);
                float4 c1 = *(const float4*)(in + j + 4);
                s += e0.x*c0.x + e0.y*c0.y + e1.x*c0.z + e1.y*c0.w
                   + e2.x*c1.x + e2.y*c1.y + e3.x*c1.z + e3.y*c1.w;
            }
        }
        s = wsum(s);
        if (lane == 0) out[row] = 1.0f / s;
        gbar();
    }
    float eri = rv[row];
    int li = lab[row];
    float s = 0.f;
    #pragma unroll
    for (int b = 0; b < 8; b++){
        int j = (b*32 + lane)*8;
        uint4 u = *(const uint4*)(E + (size_t)row*NS + j);
        float2 e0 = __bfloat1622float2(*(__nv_bfloat162*)&u.x);
        float2 e1 = __bfloat1622float2(*(__nv_bfloat162*)&u.y);
        float2 e2 = __bfloat1622float2(*(__nv_bfloat162*)&u.z);
        float2 e3 = __bfloat1622float2(*(__nv_bfloat162*)&u.w);
        float ev[8] = {e0.x,e0.y,e1.x,e1.y,e2.x,e2.y,e3.x,e3.y};
        float4 c0 = *(const float4*)(cvv + j);
        float4 c1 = *(const float4*)(cvv + j + 4);
        float cv8[8] = {c0.x,c0.y,c0.z,c0.w,c1.x,c1.y,c1.z,c1.w};
        #pragma unroll
        for (int q = 0; q < 8; q++){
            float p = ev[q] * eri * cv8[q];
            float gt = (li == lab[NS + j + q]) ? 1.f : 0.f;
            s += fabsf(p - gt);
        }
    }
    s = wsum(s);
    if (lane == 0) atomicAdd(acc + 2, (double)s);
}
__global__ __launch_bounds__(256)
void supcon_final(const float* __restrict__ es, const float* __restrict__ ps,
                  const int* __restrict__ lab, const int* __restrict__ h, double* acc){
    __shared__ float red[256];
    int i = blockIdx.x*256 + threadIdx.x;
    float cnt = (float)(h[lab[i]] - 1);
    float v = ps[i]/cnt - logf(es[i]);
    float s = bsum256(v, red);
    if (threadIdx.x == 0) atomicAdd(acc + 3, (double)s);
}
__global__ void finalize_kernel(const double* acc, float* out){
    if (threadIdx.x == 0 && blockIdx.x == 0)
        out[0] = (float)(acc[2] + 0.1 * (-(acc[3] / (double)NF)));
}

// ---------------- host ----------------
extern "C" void kernel_launch(void* const* d_in, const int* in_sizes, int n_in,
                              void* d_out, int out_size){
    const float *nodes_src=(const float*)d_in[0], *nodes_tgt=(const float*)d_in[1];
    const int *labels_src=(const int*)d_in[2], *labels_tgt=(const int*)d_in[3];
    const float *w1=(const float*)d_in[4], *b1=(const float*)d_in[5];
    const float *w2=(const float*)d_in[6], *b2=(const float*)d_in[7];
    const float *wq=(const float*)d_in[8], *wk=(const float*)d_in[9];
    const float *wv=(const float*)d_in[10], *wo=(const float*)d_in[11];
    const float *cq=(const float*)d_in[12], *ck=(const float*)d_in[13];
    const float *cv=(const float*)d_in[14], *co=(const float*)d_in[15];
    const float *Am=(const float*)d_in[16];

    __nv_bfloat16 *inb,*h1b,*x0b,*x1b,*x2b,*qb,*fnb,*qkv,*Pb,*wT;
    float *x0,*x1,*x2,*S0,*rsum,*rv,*cvv,*ep;
    double* dacc; int *lab,*hist;
    cudaGetSymbolAddress((void**)&inb,g_inb); cudaGetSymbolAddress((void**)&h1b,g_h1b);
    cudaGetSymbolAddress((void**)&x0b,g_x0b); cudaGetSymbolAddress((void**)&x1b,g_x1b);
    cudaGetSymbolAddress((void**)&x2b,g_x2b); cudaGetSymbolAddress((void**)&qb,g_qb);
    cudaGetSymbolAddress((void**)&fnb,g_fnb); cudaGetSymbolAddress((void**)&qkv,g_qkv);
    cudaGetSymbolAddress((void**)&Pb,g_Pb);   cudaGetSymbolAddress((void**)&wT,g_wT);
    cudaGetSymbolAddress((void**)&x0,g_x0);
    cudaGetSymbolAddress((void**)&x1,g_x1);   cudaGetSymbolAddress((void**)&x2,g_x2);
    cudaGetSymbolAddress((void**)&S0,g_S0);   cudaGetSymbolAddress((void**)&rsum,g_rsum);
    cudaGetSymbolAddress((void**)&rv,g_r);    cudaGetSymbolAddress((void**)&cvv,g_c);
    cudaGetSymbolAddress((void**)&ep,g_ep);   cudaGetSymbolAddress((void**)&dacc,g_dacc);
    cudaGetSymbolAddress((void**)&lab,g_lab); cudaGetSymbolAddress((void**)&hist,g_hist);
    float *esum = ep, *psum = ep + NF;
    float *rsum2 = rsum + NF;

    const int WSZ = DD*DD;
    __nv_bfloat16 *Eb = Pb, *EbT = Pb + NELEM;
    __nv_bfloat16 *Sb = (__nv_bfloat16*)S0;      // bf16 affinity matrix (8 MB of S0)
    cudaStream_t sB = g_si.s;

    // ---- fork at t=0: weight conversion + products on sB ----
    cudaEventRecord(g_si.ev[0], 0);
    cudaStreamWaitEvent(sB, g_si.ev[0], 0);
    P17 s17;
    for (int i = 0; i < 17; i++){ s17.p[i] = nullptr; s17.tr[i] = 1; s17.sc[i] = 1.0f; }
    s17.p[0]=w1; s17.p[1]=w2; s17.p[8]=Am;
    s17.p[9]=wk;  s17.tr[9]=0;
    s17.p[10]=wo;
    s17.p[11]=ck; s17.tr[11]=0;
    s17.p[12]=co;
    s17.p[13]=wq; s17.tr[13]=0; s17.sc[13]=0.0625f;
    s17.p[14]=wv; s17.tr[14]=0;
    s17.p[15]=cq; s17.tr[15]=0; s17.sc[15]=0.0625f;
    s17.p[16]=cv; s17.tr[16]=0;
    cvtT17<<<dim3(DD, 17), 256, 0, sB>>>(s17, wT);
    cudaEventRecord(g_si.ev[1], sB);

    auto TC = [&](cudaStream_t st, dim3 g, const __nv_bfloat16* A, int lda, long long azs,
                  const __nv_bfloat16* B, int ldb, long long bzs, int transB,
                  int K, int ksl, int epi, float sc, int scaleN,
                  float* oF, __nv_bfloat16* oB, int ldc, long long czs, int mzoff,
                  const float* bias_, float* rsW){
        tc_nt<<<g, 256, 0, st>>>(A, lda, azs, B, ldb, bzs, transB, K, ksl, epi, sc, scaleN,
                                 oF, oB, ldc, czs, mzoff, bias_, rsW, dacc, lab, esum, psum);
    };

    TC(sB, dim3(2,2,4), wT+9*WSZ,256,WSZ, wT+13*WSZ,256,WSZ,0, 256,1, 0, 1.f,0,
       nullptr, wT+2*WSZ, 256, (long long)WSZ, 0, nullptr,nullptr);
    cudaEventRecord(g_si.ev[2], sB);

    cudaMemsetAsync(dacc, 0, 4*sizeof(double));
    cudaMemsetAsync(hist, 0, 16*sizeof(int));
    cudaMemsetAsync(ep, 0, 2*NF*sizeof(float));
    cudaMemsetAsync(rsum, 0, 2*NF*sizeof(float));
    cudaMemcpyAsync(lab, labels_src, NS*sizeof(int), cudaMemcpyDeviceToDevice);
    cudaMemcpyAsync(lab+NS, labels_tgt, NS*sizeof(int), cudaMemcpyDeviceToDevice);
    cvt_in<<<NF, 256>>>(nodes_src, nodes_tgt, inb, lab, hist);

    cudaStreamWaitEvent(0, g_si.ev[1], 0);
    TC(0, dim3(2,32,2), inb,256,0, wT,256,0,0, 256,2, 4, 1.f,0, S0, nullptr, 256,0,0, nullptr, nullptr);
    ln2_fast<<<NF/8,256>>>(S0, b1, nullptr, h1b, 1);
    TC(0, dim3(2,32,2), h1b,256,0, wT+WSZ,256,0,0, 256,2, 4, 1.f,0, S0, nullptr, 256,0,0, nullptr, nullptr);
    ln2_fast<<<NF/8,256>>>(S0, b2, x0, x0b, 0);
    cudaStreamWaitEvent(0, g_si.ev[2], 0);

    // ---- intra attention ----
    TC(0, dim3(4,32,1), x0b,256,0, wT+2*WSZ,256,0,0, 256,1, 0, 1.f,0, nullptr, qkv, 512,0,0, nullptr,nullptr);
    TC(0, dim3(16,16,2), qkv,512,LL2, x0b,256,HALF,0, 256,1, 3, 1.f,0, nullptr, Pb, NS, NELEM, NS, nullptr, rsum);
    TC(0, dim3(2,16,8), Pb,NS,NELEM, qkv+256,512,LL2,1, NS,4, 4, 1.f,0, S0, nullptr, 256,0, NS, nullptr,nullptr);
    pv_fin<<<NF/8,256>>>(S0, rsum, x0, x1, x1b);

    // ---- cross attention ----
    TC(0, dim3(4,32,1), x1b,256,0, wT+4*WSZ,256,0,0, 256,1, 0, 1.f,0, nullptr, qkv, 512,0,0, nullptr,nullptr);
    TC(0, dim3(16,16,2), qkv,512,LL2, x1b+HALF,256,-HALF,0, 256,1, 3, 1.f,0, nullptr, Pb, NS, NELEM, NS, nullptr, rsum2);
    TC(0, dim3(2,16,8), Pb,NS,NELEM, qkv+256+LL2,512,-LL2,1, NS,4, 4, 1.f,0, S0, nullptr, 256,0, NS, nullptr,nullptr);
    pv_fin<<<NF/8,256>>>(S0, rsum2, x1, x2, x2b);

    // ---- fork 2: SupCon branch on sB ----
    cudaEventRecord(g_si.ev[3], 0);
    cudaStreamWaitEvent(sB, g_si.ev[3], 0);
    fnorm_fast<<<NF/8,256,0,sB>>>(x2, fnb);
    TC(sB, dim3(32,32,1), fnb,256,0, fnb,256,0,0, 256,1, 6, SUPCON_SCALE,0, nullptr, nullptr, 0,0,0, nullptr,nullptr);
    supcon_final<<<NF/256,256,0,sB>>>(esum, psum, lab, hist, dacc);
    cudaEventRecord(g_si.ev[4], sB);

    // ---- affinity (bf16 out + stats) + fused expT/Sinkhorn (stream 0) ----
    TC(0, dim3(2,16,1), x2b,256,0, wT+8*WSZ,256,0,0, 256,1, 0, 1.f,0, nullptr, qb, 256,0,0, nullptr,nullptr);
    TC(0, dim3(16,16,1), qb,256,0, x2b+HALF,256,0,0, 256,1, 5, 1.f,0, nullptr, Sb, NS,0,0, nullptr,nullptr);
    sinkhorn_all<<<256,256>>>(Sb, dacc, Eb, EbT, rv, cvv, lab, dacc);

    cudaStreamWaitEvent(0, g_si.ev[4], 0);
    finalize_kernel<<<1,32>>>(dacc, (float*)d_out);
}

// round 16
// speedup vs baseline: 1.0656x; 1.0656x over previous
#include <cuda_runtime.h>
#include <cuda_bf16.h>
#include <math.h>
#include <stdint.h>

#define NS 2048
#define DD 256
#define NF 4096
#define HALF ((long long)NS*DD)
#define LL2  ((long long)NS*512)
#define NELEM ((long long)NS*NS)
#define NFDD ((long long)NF*DD)
#define SUPCON_SCALE 14.285714285714286f

// ---------------- persistent streams/events ----------------
struct StreamInit {
    cudaStream_t s;
    cudaEvent_t ev[6];
    StreamInit(){
        cudaStreamCreateWithFlags(&s, cudaStreamNonBlocking);
        for (int i = 0; i < 6; i++) cudaEventCreateWithFlags(&ev[i], cudaEventDisableTiming);
    }
};
static StreamInit g_si;

// ---------------- helpers ----------------
__device__ __forceinline__ uint32_t smem_to_u32(const void* p){
    uint32_t a;
    asm("{ .reg .u64 t; cvta.to.shared.u64 t, %1; cvt.u32.u64 %0, t; }" : "=r"(a) : "l"(p));
    return a;
}
__device__ __forceinline__ void cp16(void* s, const void* g){
    uint32_t sa = smem_to_u32(s);
    asm volatile("cp.async.ca.shared.global [%0], [%1], 16;" :: "r"(sa), "l"(g) : "memory");
}
__device__ __forceinline__ void ldsm_x4(uint32_t* r, uint32_t addr){
    asm volatile("ldmatrix.sync.aligned.m8n8.x4.shared.b16 {%0,%1,%2,%3}, [%4];"
        : "=r"(r[0]), "=r"(r[1]), "=r"(r[2]), "=r"(r[3]) : "r"(addr));
}
__device__ __forceinline__ void ldsm_x2(uint32_t* r, uint32_t addr){
    asm volatile("ldmatrix.sync.aligned.m8n8.x2.shared.b16 {%0,%1}, [%2];"
        : "=r"(r[0]), "=r"(r[1]) : "r"(addr));
}
__device__ __forceinline__ void ldsm_x2t(uint32_t* r, uint32_t addr){
    asm volatile("ldmatrix.sync.aligned.m8n8.x2.trans.shared.b16 {%0,%1}, [%2];"
        : "=r"(r[0]), "=r"(r[1]) : "r"(addr));
}
__device__ __forceinline__ void mma16816(float* c, const uint32_t* a, const uint32_t* b){
    asm volatile("mma.sync.aligned.m16n8k16.row.col.f32.bf16.bf16.f32 "
        "{%0,%1,%2,%3}, {%4,%5,%6,%7}, {%8,%9}, {%0,%1,%2,%3};"
        : "+f"(c[0]), "+f"(c[1]), "+f"(c[2]), "+f"(c[3])
        : "r"(a[0]), "r"(a[1]), "r"(a[2]), "r"(a[3]), "r"(b[0]), "r"(b[1]));
}
__device__ __forceinline__ float fexp(float x){
    float t = x * 1.4426950408889634f;
    float r = rintf(t);
    float f = t - r;
    float p =            1.3333558146e-3f;
    p = fmaf(p, f, 9.6181291076e-3f);
    p = fmaf(p, f, 5.5504108664e-2f);
    p = fmaf(p, f, 2.4022650696e-1f);
    p = fmaf(p, f, 6.9314718056e-1f);
    p = fmaf(p, f, 1.0f);
    float res = __int_as_float(__float_as_int(p) + (((int)r) << 23));
    return (x < -87.0f) ? 0.0f : res;
}
__device__ __forceinline__ float bsum256(float v, float* red){
    int tid = threadIdx.x;
    red[tid] = v; __syncthreads();
    #pragma unroll
    for (int o = 128; o > 0; o >>= 1){
        if (tid < o) red[tid] += red[tid + o];
        __syncthreads();
    }
    float r = red[0]; __syncthreads();
    return r;
}
__device__ __forceinline__ float wsum(float v){
    #pragma unroll
    for (int o = 16; o > 0; o >>= 1) v += __shfl_xor_sync(0xffffffffu, v, o);
    return v;
}

// ---------------- scratch ----------------
__device__ __nv_bfloat16 g_inb[NF*DD], g_h1b[NF*DD], g_x0b[NF*DD], g_x1b[NF*DD], g_x2b[NF*DD];
__device__ __nv_bfloat16 g_qb[NF*DD], g_fnb[NF*DD];
__device__ __nv_bfloat16 g_qkv[(long long)NF*512];
__device__ __nv_bfloat16 g_Pb[2*NELEM];
__device__ __nv_bfloat16 g_wT[17*DD*DD];
__device__ float g_x0[NF*DD], g_x1[NF*DD], g_x2[NF*DD];
__device__ float g_S0[NELEM];
__device__ float g_rsum[2*NF], g_r[NS], g_c[NS], g_ep[2*NF];
__device__ double g_dacc[4];
__device__ int g_lab[NF], g_hist[16];
__device__ int g_cnt;
__device__ volatile int g_epoch;

// ============================================================================
// Generic bf16 HMMA NT/NN GEMM, 128x128 tile, K-chunk 64, double-buffered
// cp.async (proven R13 mainloop).
// epi: 0 bf16 | 1 f32+bias | 3 exp+rowsum+bf16 | 4 split-K f32 slice
//      5 bf16 store + stats | 6 supcon triangular row+col
// ============================================================================
__global__ __launch_bounds__(256)
void tc_nt(const __nv_bfloat16* A, int lda, long long azs,
           const __nv_bfloat16* B, int ldb, long long bzs, int transB,
           int K, int ksl, int epi, float scale, int scaleN,
           float* outF, __nv_bfloat16* outB, int ldc, long long czs, int mzoff,
           const float* bias, float* rsumW, double* dacc,
           const int* lab, float* esum, float* psum)
{
    if (epi == 6 && blockIdx.x < blockIdx.y) return;
    __shared__ __nv_bfloat16 SA[2][128*72];
    __shared__ __nv_bfloat16 SB[2][128*72];
    __shared__ float red[256];

    int z = blockIdx.z;
    int dom = z / ksl, kk = z - dom*ksl;
    A += (long long)dom * azs;
    B += (long long)dom * bzs;
    if (outB) outB += (long long)dom * czs;

    int tid = threadIdx.x, wid = tid >> 5, lane = tid & 31;
    int wr = wid >> 2, wc = wid & 3;
    int row0 = blockIdx.y * 128, col0 = blockIdx.x * 128;

    float acc[4][4][4];
    #pragma unroll
    for (int mi = 0; mi < 4; mi++)
        #pragma unroll
        for (int ni = 0; ni < 4; ni++)
            #pragma unroll
            for (int q = 0; q < 4; q++) acc[mi][ni][q] = 0.f;

    int aRow  = wr*64 + (lane & 7) + ((lane >> 3) & 1)*8;
    int aKoff = (lane >> 4)*8;
    int l16   = lane & 15;
    int bRow  = wc*32 + (l16 & 7);
    int bKoff = (l16 >> 3)*8;

    int nch = K >> 6;
    int c0ch = kk * nch / ksl, c1ch = (kk+1) * nch / ksl;

    auto load_chunk = [&](int c, int buf){
        int kc = c << 6;
        #pragma unroll
        for (int i = 0; i < 4; i++){
            int lin = i*256 + tid;
            int r = lin >> 3, c8 = (lin & 7) << 3;
            cp16(&SA[buf][r*72 + c8], A + (size_t)(row0+r)*lda + kc + c8);
        }
        if (!transB){
            #pragma unroll
            for (int i = 0; i < 4; i++){
                int lin = i*256 + tid;
                int r = lin >> 3, c8 = (lin & 7) << 3;
                cp16(&SB[buf][r*72 + c8], B + (size_t)(col0+r)*ldb + kc + c8);
            }
        } else {
            #pragma unroll
            for (int i = 0; i < 4; i++){
                int lin = i*256 + tid;
                int r = lin >> 4, c8 = (lin & 15) << 3;
                cp16(&SB[buf][r*136 + c8], B + (size_t)(kc+r)*ldb + col0 + c8);
            }
        }
    };

    load_chunk(c0ch, 0);
    asm volatile("cp.async.commit_group;" ::: "memory");
    asm volatile("cp.async.wait_group 0;" ::: "memory");
    __syncthreads();

    for (int c = c0ch; c < c1ch; c++){
        int buf = (c - c0ch) & 1;
        if (c + 1 < c1ch){
            load_chunk(c+1, buf^1);
            asm volatile("cp.async.commit_group;" ::: "memory");
        }
        uint32_t sAb = smem_to_u32(SA[buf]);
        uint32_t sBb = smem_to_u32(SB[buf]);
        #pragma unroll
        for (int ks = 0; ks < 4; ks++){
            uint32_t af[4][4], bf[4][2];
            #pragma unroll
            for (int mi = 0; mi < 4; mi++)
                ldsm_x4(af[mi], sAb + (uint32_t)(((aRow + mi*16)*72 + ks*16 + aKoff) * 2));
            if (!transB){
                #pragma unroll
                for (int ni = 0; ni < 4; ni++)
                    ldsm_x2(bf[ni], sBb + (uint32_t)(((bRow + ni*8)*72 + ks*16 + bKoff) * 2));
            } else {
                #pragma unroll
                for (int ni = 0; ni < 4; ni++)
                    ldsm_x2t(bf[ni], sBb + (uint32_t)(((ks*16 + l16)*136 + wc*32 + ni*8) * 2));
            }
            #pragma unroll
            for (int mi = 0; mi < 4; mi++)
                #pragma unroll
                for (int ni = 0; ni < 4; ni++)
                    mma16816(acc[mi][ni], af[mi], bf[ni]);
        }
        if (c + 1 < c1ch)
            asm volatile("cp.async.wait_group 0;" ::: "memory");
        __syncthreads();
    }

    int lr = lane >> 2, lc2 = (lane & 3) << 1;
    int colB = col0 + wc*32;
    float s1 = 0.f, s2 = 0.f;
    bool diag = (blockIdx.x == blockIdx.y);
    float colE[8], colS[8];
    #pragma unroll
    for (int q = 0; q < 8; q++){ colE[q] = 0.f; colS[q] = 0.f; }
    int labc[8];
    if (epi == 6){
        #pragma unroll
        for (int ni = 0; ni < 4; ni++){
            labc[ni*2]   = lab[colB + ni*8 + lc2];
            labc[ni*2+1] = lab[colB + ni*8 + lc2 + 1];
        }
    }

    #pragma unroll
    for (int mi = 0; mi < 4; mi++){
        #pragma unroll
        for (int h = 0; h < 2; h++){
            int r = row0 + wr*64 + mi*16 + lr + h*8;
            if (epi == 0){
                #pragma unroll
                for (int ni = 0; ni < 4; ni++){
                    int cc = colB + ni*8 + lc2;
                    float m0 = (cc   < scaleN) ? scale : 1.0f;
                    float m1 = (cc+1 < scaleN) ? scale : 1.0f;
                    float v0 = acc[mi][ni][h*2+0]*m0, v1 = acc[mi][ni][h*2+1]*m1;
                    *(__nv_bfloat162*)(outB + (size_t)r*ldc + cc) = __floats2bfloat162_rn(v0, v1);
                }
            } else if (epi == 1){
                #pragma unroll
                for (int ni = 0; ni < 4; ni++){
                    int cc = colB + ni*8 + lc2;
                    float2 o = make_float2(acc[mi][ni][h*2+0] + bias[cc],
                                           acc[mi][ni][h*2+1] + bias[cc+1]);
                    *(float2*)(outF + (size_t)r*ldc + cc) = o;
                }
            } else if (epi == 3){
                float part = 0.f;
                #pragma unroll
                for (int ni = 0; ni < 4; ni++){
                    int cc = colB + ni*8 + lc2;
                    float e0 = fexp(acc[mi][ni][h*2+0]), e1 = fexp(acc[mi][ni][h*2+1]);
                    part += e0 + e1;
                    *(__nv_bfloat162*)(outB + (size_t)r*ldc + cc) = __floats2bfloat162_rn(e0, e1);
                }
                part += __shfl_xor_sync(0xffffffffu, part, 1);
                part += __shfl_xor_sync(0xffffffffu, part, 2);
                if ((lane & 3) == 0) atomicAdd(&rsumW[dom*mzoff + r], part);
            } else if (epi == 4){
                int mg = dom*mzoff + r;
                #pragma unroll
                for (int ni = 0; ni < 4; ni++){
                    int cc = colB + ni*8 + lc2;
                    *(float2*)(outF + (long long)kk*NFDD + (size_t)mg*ldc + cc) =
                        make_float2(acc[mi][ni][h*2+0], acc[mi][ni][h*2+1]);
                }
            } else if (epi == 5){
                #pragma unroll
                for (int ni = 0; ni < 4; ni++){
                    int cc = colB + ni*8 + lc2;
                    float v0 = acc[mi][ni][h*2+0], v1 = acc[mi][ni][h*2+1];
                    *(__nv_bfloat162*)(outB + (size_t)r*ldc + cc) = __floats2bfloat162_rn(v0, v1);
                    s1 += v0 + v1; s2 += v0*v0 + v1*v1;
                }
            } else {
                int rlab = lab[r];
                float pe = 0.f, ps = 0.f;
                #pragma unroll
                for (int ni = 0; ni < 4; ni++){
                    int cc = colB + ni*8 + lc2;
                    float l0 = acc[mi][ni][h*2+0]*scale, l1 = acc[mi][ni][h*2+1]*scale;
                    bool m0 = (labc[ni*2]   == rlab);
                    bool m1 = (labc[ni*2+1] == rlab);
                    if (cc != r){
                        float e = fexp(l0);
                        pe += e; if (m0) ps += l0;
                        if (!diag){ colE[ni*2] += e; if (m0) colS[ni*2] += l0; }
                    }
                    if (cc+1 != r){
                        float e = fexp(l1);
                        pe += e; if (m1) ps += l1;
                        if (!diag){ colE[ni*2+1] += e; if (m1) colS[ni*2+1] += l1; }
                    }
                }
                pe += __shfl_xor_sync(0xffffffffu, pe, 1);
                pe += __shfl_xor_sync(0xffffffffu, pe, 2);
                ps += __shfl_xor_sync(0xffffffffu, ps, 1);
                ps += __shfl_xor_sync(0xffffffffu, ps, 2);
                if ((lane & 3) == 0){
                    atomicAdd(&esum[r], pe);
                    atomicAdd(&psum[r], ps);
                }
            }
        }
    }
    if (epi == 6 && !diag){
        #pragma unroll
        for (int q = 0; q < 8; q++){
            #pragma unroll
            for (int o = 4; o <= 16; o <<= 1){
                colE[q] += __shfl_xor_sync(0xffffffffu, colE[q], o);
                colS[q] += __shfl_xor_sync(0xffffffffu, colS[q], o);
            }
        }
        if (lane < 4){
            #pragma unroll
            for (int ni = 0; ni < 4; ni++){
                int cc = col0 + wc*32 + ni*8 + lane*2;
                atomicAdd(&esum[cc],   colE[ni*2]);
                atomicAdd(&psum[cc],   colS[ni*2]);
                atomicAdd(&esum[cc+1], colE[ni*2+1]);
                atomicAdd(&psum[cc+1], colS[ni*2+1]);
            }
        }
    }
    if (epi == 5){
        float bs = bsum256(s1, red), bss = bsum256(s2, red);
        if (tid == 0){ atomicAdd(dacc, (double)bs); atomicAdd(dacc+1, (double)bss); }
    }
}

// ---------------- small kernels ----------------
__global__ __launch_bounds__(256)
void cvt_in(const float* __restrict__ a, const float* __restrict__ b,
            __nv_bfloat16* __restrict__ o, const int* __restrict__ lab, int* hist){
    int i = blockIdx.x, t = threadIdx.x;
    const float* src = (i < NS) ? a + (size_t)i*DD : b + (size_t)(i-NS)*DD;
    o[(size_t)i*DD + t] = __float2bfloat16(src[t]);
    if (t == 0) atomicAdd(&hist[lab[i]], 1);
}
struct P17 { const float* p[17]; int tr[17]; float sc[17]; };
__global__ __launch_bounds__(256)
void cvtT17(P17 s, __nv_bfloat16* __restrict__ o){
    int w = blockIdx.y, n = blockIdx.x, k = threadIdx.x;
    const float* src = s.p[w];
    if (!src) return;
    float v = s.tr[w] ? src[(size_t)k*DD + n] : src[(size_t)n*DD + k];
    o[(size_t)w*DD*DD + (size_t)n*DD + k] = __float2bfloat16(v * s.sc[w]);
}
__global__ __launch_bounds__(256)
void ln2_fast(const float* __restrict__ S, const float* __restrict__ bias,
              float* __restrict__ outF, __nv_bfloat16* __restrict__ outB, int relu){
    int wid = threadIdx.x >> 5, lane = threadIdx.x & 31;
    int i = blockIdx.x*8 + wid;
    size_t off = (size_t)i*DD + lane*8;
    float4 a0 = *(const float4*)(S + off);
    float4 b0 = *(const float4*)(S + off + 4);
    float4 a1 = *(const float4*)(S + NFDD + off);
    float4 b1 = *(const float4*)(S + NFDD + off + 4);
    const float* bp = bias + lane*8;
    float v[8];
    v[0]=a0.x+a1.x+bp[0]; v[1]=a0.y+a1.y+bp[1]; v[2]=a0.z+a1.z+bp[2]; v[3]=a0.w+a1.w+bp[3];
    v[4]=b0.x+b1.x+bp[4]; v[5]=b0.y+b1.y+bp[5]; v[6]=b0.z+b1.z+bp[6]; v[7]=b0.w+b1.w+bp[7];
    float s = 0.f, ss = 0.f;
    #pragma unroll
    for (int q = 0; q < 8; q++){ s += v[q]; ss += v[q]*v[q]; }
    s = wsum(s); ss = wsum(ss);
    float m = s*(1.f/DD);
    float k = rsqrtf(ss*(1.f/DD) - m*m + 1e-5f);
    __nv_bfloat162 ob[4];
    #pragma unroll
    for (int q = 0; q < 4; q++){
        float o0 = (v[2*q]   - m)*k;
        float o1 = (v[2*q+1] - m)*k;
        if (relu){ o0 = fmaxf(o0, 0.f); o1 = fmaxf(o1, 0.f); }
        if (outF) *(float2*)(outF + off + 2*q) = make_float2(o0, o1);
        ob[q] = __floats2bfloat162_rn(o0, o1);
    }
    *(uint4*)(outB + off) = *(uint4*)ob;
}
__global__ __launch_bounds__(256)
void fnorm_fast(const float* __restrict__ X, __nv_bfloat16* __restrict__ F){
    int wid = threadIdx.x >> 5, lane = threadIdx.x & 31;
    int i = blockIdx.x*8 + wid;
    const float* xp = X + (size_t)i*DD + lane*8;
    float4 a = *(const float4*)xp;
    float4 b = *(const float4*)(xp + 4);
    float ss = a.x*a.x+a.y*a.y+a.z*a.z+a.w*a.w + b.x*b.x+b.y*b.y+b.z*b.z+b.w*b.w;
    ss = wsum(ss);
    float k = 1.0f / (sqrtf(ss) + 1e-8f);
    float v[8] = {a.x,a.y,a.z,a.w,b.x,b.y,b.z,b.w};
    __nv_bfloat162 ob[4];
    #pragma unroll
    for (int q = 0; q < 4; q++)
        ob[q] = __floats2bfloat162_rn(v[2*q]*k, v[2*q+1]*k);
    *(uint4*)(F + (size_t)i*DD + lane*8) = *(uint4*)ob;
}
__global__ __launch_bounds__(256)
void pv_fin(const float* __restrict__ acc4, const float* __restrict__ rsum,
            const float* __restrict__ res, float* __restrict__ outF,
            __nv_bfloat16* __restrict__ outB){
    int wid = threadIdx.x >> 5, lane = threadIdx.x & 31;
    int i = blockIdx.x*8 + wid;
    float rinv = 1.0f / rsum[i];
    size_t off = (size_t)i*DD + lane*8;
    float v[8];
    #pragma unroll
    for (int q = 0; q < 8; q++) v[q] = 0.f;
    #pragma unroll
    for (int sl = 0; sl < 4; sl++){
        const float* p = acc4 + (long long)sl*NFDD + off;
        float4 a = *(const float4*)p;
        float4 b = *(const float4*)(p + 4);
        v[0]+=a.x; v[1]+=a.y; v[2]+=a.z; v[3]+=a.w;
        v[4]+=b.x; v[5]+=b.y; v[6]+=b.z; v[7]+=b.w;
    }
    const float* rp = res + off;
    float4 ra = *(const float4*)rp;
    float4 rb = *(const float4*)(rp + 4);
    float rr[8] = {ra.x,ra.y,ra.z,ra.w,rb.x,rb.y,rb.z,rb.w};
    __nv_bfloat162 ob[4];
    #pragma unroll
    for (int q = 0; q < 4; q++){
        float o0 = fmaf(v[2*q],   rinv, rr[2*q]);
        float o1 = fmaf(v[2*q+1], rinv, rr[2*q+1]);
        *(float2*)(outF + off + 2*q) = make_float2(o0, o1);
        ob[q] = __floats2bfloat162_rn(o0, o1);
    }
    *(uint4*)(outB + off) = *(uint4*)ob;
}
// Persistent: phase0 builds E/ET from bf16 Sb + stats, then 20 passes + match.
__global__ __launch_bounds__(256)
void sinkhorn_all(const __nv_bfloat16* __restrict__ Sb, const double* __restrict__ dacc,
                  __nv_bfloat16* __restrict__ E, __nv_bfloat16* __restrict__ ET,
                  float* __restrict__ rv, float* __restrict__ cvv,
                  const int* __restrict__ lab, double* acc){
    __shared__ float sm[64][68];
    int tid = threadIdx.x, wid = tid >> 5, lane = tid & 31;
    int row = blockIdx.x*8 + wid;
    int nb = gridDim.x;

    {
        double n = (double)NELEM;
        double mu_d = dacc[0] / n;
        double var = dacc[1] / n - mu_d*mu_d;
        float inv = (float)(1.0 / (sqrt(var) + 1e-5));
        float muinv = (float)mu_d * inv;
        for (int t4 = 0; t4 < 4; t4++){
            int tile = t4*256 + blockIdx.x;
            int r0 = (tile >> 5)*64, c0 = (tile & 31)*64;
            #pragma unroll
            for (int i = 0; i < 2; i++){
                int lin = i*256 + tid;
                int r = lin >> 3, c8 = (lin & 7) << 3;
                uint4 u = *(const uint4*)(Sb + (size_t)(r0+r)*NS + c0 + c8);
                float2 v0 = __bfloat1622float2(*(__nv_bfloat162*)&u.x);
                float2 v1 = __bfloat1622float2(*(__nv_bfloat162*)&u.y);
                float2 v2 = __bfloat1622float2(*(__nv_bfloat162*)&u.z);
                float2 v3 = __bfloat1622float2(*(__nv_bfloat162*)&u.w);
                sm[r][c8+0] = fexp(fmaf(v0.x, inv, -muinv));
                sm[r][c8+1] = fexp(fmaf(v0.y, inv, -muinv));
                sm[r][c8+2] = fexp(fmaf(v1.x, inv, -muinv));
                sm[r][c8+3] = fexp(fmaf(v1.y, inv, -muinv));
                sm[r][c8+4] = fexp(fmaf(v2.x, inv, -muinv));
                sm[r][c8+5] = fexp(fmaf(v2.y, inv, -muinv));
                sm[r][c8+6] = fexp(fmaf(v3.x, inv, -muinv));
                sm[r][c8+7] = fexp(fmaf(v3.y, inv, -muinv));
            }
            __syncthreads();
            #pragma unroll
            for (int i = 0; i < 2; i++){
                int lin = i*256 + tid;
                int r = lin >> 3, g8 = (lin & 7) << 3;
                __nv_bfloat162 ob[4];
                #pragma unroll
                for (int q = 0; q < 4; q++)
                    ob[q] = __floats2bfloat162_rn(sm[r][g8+2*q], sm[r][g8+2*q+1]);
                *(uint4*)(E + (size_t)(r0+r)*NS + c0 + g8) = *(uint4*)ob;
                #pragma unroll
                for (int q = 0; q < 4; q++)
                    ob[q] = __floats2bfloat162_rn(sm[g8+2*q][r], sm[g8+2*q+1][r]);
                *(uint4*)(ET + (size_t)(c0+r)*NS + r0 + g8) = *(uint4*)ob;
            }
            __syncthreads();
        }
    }
    auto gbar = [&](){
        __threadfence();
        __syncthreads();
        if (tid == 0){
            int e = g_epoch;
            if (atomicAdd(&g_cnt, 1) == nb - 1){
                g_cnt = 0;
                __threadfence();
                g_epoch = e + 1;
            } else {
                while (g_epoch == e) { }
            }
            __threadfence();
        }
        __syncthreads();
    };
    gbar();

    for (int pass = 0; pass < 20; pass++){
        const __nv_bfloat16* M = (pass & 1) ? ET : E;
        const float* in = (pass & 1) ? rv : cvv;
        float* out = (pass & 1) ? cvv : rv;
        float s = 0.f;
        #pragma unroll
        for (int b = 0; b < 8; b++){
            int j = (b*32 + lane)*8;
            uint4 u = *(const uint4*)(M + (size_t)row*NS + j);
            float2 e0 = __bfloat1622float2(*(__nv_bfloat162*)&u.x);
            float2 e1 = __bfloat1622float2(*(__nv_bfloat162*)&u.y);
            float2 e2 = __bfloat1622float2(*(__nv_bfloat162*)&u.z);
            float2 e3 = __bfloat1622float2(*(__nv_bfloat162*)&u.w);
            if (pass == 0){
                s += e0.x+e0.y+e1.x+e1.y+e2.x+e2.y+e3.x+e3.y;
            } else {
                float4 c0 = *(const float4*)(in + j);
                float4 c1 = *(const float4*)(in + j + 4);
                s += e0.x*c0.x + e0.y*c0.y + e1.x*c0.z + e1.y*c0.w
                   + e2.x*c1.x + e2.y*c1.y + e3.x*c1.z + e3.y*c1.w;
            }
        }
        s = wsum(s);
        if (lane == 0) out[row] = 1.0f / s;
        gbar();
    }
    float eri = rv[row];
    int li = lab[row];
    float s = 0.f;
    #pragma unroll
    for (int b = 0; b < 8; b++){
        int j = (b*32 + lane)*8;
        uint4 u = *(const uint4*)(E + (size_t)row*NS + j);
        float2 e0 = __bfloat1622float2(*(__nv_bfloat162*)&u.x);
        float2 e1 = __bfloat1622float2(*(__nv_bfloat162*)&u.y);
        float2 e2 = __bfloat1622float2(*(__nv_bfloat162*)&u.z);
        float2 e3 = __bfloat1622float2(*(__nv_bfloat162*)&u.w);
        float ev[8] = {e0.x,e0.y,e1.x,e1.y,e2.x,e2.y,e3.x,e3.y};
        float4 c0 = *(const float4*)(cvv + j);
        float4 c1 = *(const float4*)(cvv + j + 4);
        float cv8[8] = {c0.x,c0.y,c0.z,c0.w,c1.x,c1.y,c1.z,c1.w};
        #pragma unroll
        for (int q = 0; q < 8; q++){
            float p = ev[q] * eri * cv8[q];
            float gt = (li == lab[NS + j + q]) ? 1.f : 0.f;
            s += fabsf(p - gt);
        }
    }
    s = wsum(s);
    if (lane == 0) atomicAdd(acc + 2, (double)s);
}
__global__ __launch_bounds__(256)
void supcon_final(const float* __restrict__ es, const float* __restrict__ ps,
                  const int* __restrict__ lab, const int* __restrict__ h, double* acc){
    __shared__ float red[256];
    int i = blockIdx.x*256 + threadIdx.x;
    float cnt = (float)(h[lab[i]] - 1);
    float v = ps[i]/cnt - logf(es[i]);
    float s = bsum256(v, red);
    if (threadIdx.x == 0) atomicAdd(acc + 3, (double)s);
}
__global__ void finalize_kernel(const double* acc, float* out){
    if (threadIdx.x == 0 && blockIdx.x == 0)
        out[0] = (float)(acc[2] + 0.1 * (-(acc[3] / (double)NF)));
}

// ---------------- host ----------------
extern "C" void kernel_launch(void* const* d_in, const int* in_sizes, int n_in,
                              void* d_out, int out_size){
    const float *nodes_src=(const float*)d_in[0], *nodes_tgt=(const float*)d_in[1];
    const int *labels_src=(const int*)d_in[2], *labels_tgt=(const int*)d_in[3];
    const float *w1=(const float*)d_in[4], *b1=(const float*)d_in[5];
    const float *w2=(const float*)d_in[6], *b2=(const float*)d_in[7];
    const float *wq=(const float*)d_in[8], *wk=(const float*)d_in[9];
    const float *wv=(const float*)d_in[10], *wo=(const float*)d_in[11];
    const float *cq=(const float*)d_in[12], *ck=(const float*)d_in[13];
    const float *cv=(const float*)d_in[14], *co=(const float*)d_in[15];
    const float *Am=(const float*)d_in[16];

    __nv_bfloat16 *inb,*h1b,*x0b,*x1b,*x2b,*qb,*fnb,*qkv,*Pb,*wT;
    float *x0,*x1,*x2,*S0,*rsum,*rv,*cvv,*ep;
    double* dacc; int *lab,*hist;
    cudaGetSymbolAddress((void**)&inb,g_inb); cudaGetSymbolAddress((void**)&h1b,g_h1b);
    cudaGetSymbolAddress((void**)&x0b,g_x0b); cudaGetSymbolAddress((void**)&x1b,g_x1b);
    cudaGetSymbolAddress((void**)&x2b,g_x2b); cudaGetSymbolAddress((void**)&qb,g_qb);
    cudaGetSymbolAddress((void**)&fnb,g_fnb); cudaGetSymbolAddress((void**)&qkv,g_qkv);
    cudaGetSymbolAddress((void**)&Pb,g_Pb);   cudaGetSymbolAddress((void**)&wT,g_wT);
    cudaGetSymbolAddress((void**)&x0,g_x0);
    cudaGetSymbolAddress((void**)&x1,g_x1);   cudaGetSymbolAddress((void**)&x2,g_x2);
    cudaGetSymbolAddress((void**)&S0,g_S0);   cudaGetSymbolAddress((void**)&rsum,g_rsum);
    cudaGetSymbolAddress((void**)&rv,g_r);    cudaGetSymbolAddress((void**)&cvv,g_c);
    cudaGetSymbolAddress((void**)&ep,g_ep);   cudaGetSymbolAddress((void**)&dacc,g_dacc);
    cudaGetSymbolAddress((void**)&lab,g_lab); cudaGetSymbolAddress((void**)&hist,g_hist);
    float *esum = ep, *psum = ep + NF;
    float *rsum2 = rsum + NF;

    const int WSZ = DD*DD;
    __nv_bfloat16 *Eb = Pb, *EbT = Pb + NELEM;
    __nv_bfloat16 *Sb = (__nv_bfloat16*)S0;
    cudaStream_t sB = g_si.s;

    // ---- fork at t=0: weight conversion + products on sB ----
    cudaEventRecord(g_si.ev[0], 0);
    cudaStreamWaitEvent(sB, g_si.ev[0], 0);
    P17 s17;
    for (int i = 0; i < 17; i++){ s17.p[i] = nullptr; s17.tr[i] = 1; s17.sc[i] = 1.0f; }
    s17.p[0]=w1; s17.p[1]=w2; s17.p[8]=Am;
    s17.p[9]=wk;  s17.tr[9]=0;
    s17.p[10]=wo;
    s17.p[11]=ck; s17.tr[11]=0;
    s17.p[12]=co;
    s17.p[13]=wq; s17.tr[13]=0; s17.sc[13]=0.0625f;
    s17.p[14]=wv; s17.tr[14]=0;
    s17.p[15]=cq; s17.tr[15]=0; s17.sc[15]=0.0625f;
    s17.p[16]=cv; s17.tr[16]=0;
    cvtT17<<<dim3(DD, 17), 256, 0, sB>>>(s17, wT);
    cudaEventRecord(g_si.ev[1], sB);

    auto TC = [&](cudaStream_t st, dim3 g, const __nv_bfloat16* A, int lda, long long azs,
                  const __nv_bfloat16* B, int ldb, long long bzs, int transB,
                  int K, int ksl, int epi, float sc, int scaleN,
                  float* oF, __nv_bfloat16* oB, int ldc, long long czs, int mzoff,
                  const float* bias_, float* rsW){
        tc_nt<<<g, 256, 0, st>>>(A, lda, azs, B, ldb, bzs, transB, K, ksl, epi, sc, scaleN,
                                 oF, oB, ldc, czs, mzoff, bias_, rsW, dacc, lab, esum, psum);
    };

    TC(sB, dim3(2,2,4), wT+9*WSZ,256,WSZ, wT+13*WSZ,256,WSZ,0, 256,1, 0, 1.f,0,
       nullptr, wT+2*WSZ, 256, (long long)WSZ, 0, nullptr,nullptr);
    cudaEventRecord(g_si.ev[2], sB);

    cudaMemsetAsync(dacc, 0, 4*sizeof(double));
    cudaMemsetAsync(hist, 0, 16*sizeof(int));
    cudaMemsetAsync(ep, 0, 2*NF*sizeof(float));
    cudaMemsetAsync(rsum, 0, 2*NF*sizeof(float));
    cudaMemcpyAsync(lab, labels_src, NS*sizeof(int), cudaMemcpyDeviceToDevice);
    cudaMemcpyAsync(lab+NS, labels_tgt, NS*sizeof(int), cudaMemcpyDeviceToDevice);
    cvt_in<<<NF, 256>>>(nodes_src, nodes_tgt, inb, lab, hist);

    cudaStreamWaitEvent(0, g_si.ev[1], 0);
    TC(0, dim3(2,32,2), inb,256,0, wT,256,0,0, 256,2, 4, 1.f,0, S0, nullptr, 256,0,0, nullptr, nullptr);
    ln2_fast<<<NF/8,256>>>(S0, b1, nullptr, h1b, 1);
    TC(0, dim3(2,32,2), h1b,256,0, wT+WSZ,256,0,0, 256,2, 4, 1.f,0, S0, nullptr, 256,0,0, nullptr, nullptr);
    ln2_fast<<<NF/8,256>>>(S0, b2, x0, x0b, 0);
    cudaStreamWaitEvent(0, g_si.ev[2], 0);

    // ---- intra attention ----
    TC(0, dim3(4,32,1), x0b,256,0, wT+2*WSZ,256,0,0, 256,1, 0, 1.f,0, nullptr, qkv, 512,0,0, nullptr,nullptr);
    TC(0, dim3(16,16,2), qkv,512,LL2, x0b,256,HALF,0, 256,1, 3, 1.f,0, nullptr, Pb, NS, NELEM, NS, nullptr, rsum);
    TC(0, dim3(2,16,8), Pb,NS,NELEM, qkv+256,512,LL2,1, NS,4, 4, 1.f,0, S0, nullptr, 256,0, NS, nullptr,nullptr);
    pv_fin<<<NF/8,256>>>(S0, rsum, x0, x1, x1b);

    // ---- cross attention ----
    TC(0, dim3(4,32,1), x1b,256,0, wT+4*WSZ,256,0,0, 256,1, 0, 1.f,0, nullptr, qkv, 512,0,0, nullptr,nullptr);
    TC(0, dim3(16,16,2), qkv,512,LL2, x1b+HALF,256,-HALF,0, 256,1, 3, 1.f,0, nullptr, Pb, NS, NELEM, NS, nullptr, rsum2);
    TC(0, dim3(2,16,8), Pb,NS,NELEM, qkv+256+LL2,512,-LL2,1, NS,4, 4, 1.f,0, S0, nullptr, 256,0, NS, nullptr,nullptr);
    pv_fin<<<NF/8,256>>>(S0, rsum2, x1, x2, x2b);

    // ---- fork 2: SupCon branch on sB ----
    cudaEventRecord(g_si.ev[3], 0);
    cudaStreamWaitEvent(sB, g_si.ev[3], 0);
    fnorm_fast<<<NF/8,256,0,sB>>>(x2, fnb);
    TC(sB, dim3(32,32,1), fnb,256,0, fnb,256,0,0, 256,1, 6, SUPCON_SCALE,0, nullptr, nullptr, 0,0,0, nullptr,nullptr);
    supcon_final<<<NF/256,256,0,sB>>>(esum, psum, lab, hist, dacc);
    cudaEventRecord(g_si.ev[4], sB);

    // ---- affinity (bf16 out + stats) + fused expT/Sinkhorn (stream 0) ----
    TC(0, dim3(2,16,1), x2b,256,0, wT+8*WSZ,256,0,0, 256,1, 0, 1.f,0, nullptr, qb, 256,0,0, nullptr,nullptr);
    TC(0, dim3(16,16,1), qb,256,0, x2b+HALF,256,0,0, 256,1, 5, 1.f,0, nullptr, Sb, NS,0,0, nullptr,nullptr);
    sinkhorn_all<<<256,256>>>(Sb, dacc, Eb, EbT, rv, cvv, lab, dacc);

    cudaStreamWaitEvent(0, g_si.ev[4], 0);
    finalize_kernel<<<1,32>>>(dacc, (float*)d_out);
}